// round 7
// baseline (speedup 1.0000x reference)
#include <cuda_runtime.h>

// ---------------------------------------------------------------------------
// CarryII R7: R6 + dst-chunked zero/scatter to eliminate atomic RFO reads.
// Per relation: for each ~64MB chunk of output rows [lo,hi):
//   1) zero the chunk (dirty lines stay in 126MB L2),
//   2) scatter pass over ALL edges, predicated on dst in [lo,hi).
// REDs then hit L2-dirty lines -> no DRAM read-for-ownership; each output
// line does exactly one DRAM write (the eventual writeback).
// Gathers use __ldcs (evict-first) so feature lines don't evict the chunk.
// Extra cost: d_idx re-read once per chunk (~8MB << RFO saved).
// ---------------------------------------------------------------------------

static constexpr int FEAT_D = 32;
static constexpr int CHUNK_ROWS = 512 * 1024;   // 512k rows * 128B = 64 MB

__global__ void zero_f4_kernel(float4* __restrict__ out, long long n4) {
    long long i = blockIdx.x * (long long)blockDim.x + threadIdx.x;
    if (i < n4) out[i] = make_float4(0.f, 0.f, 0.f, 0.f);
}

__device__ __forceinline__ void red_add_v4(float* addr, float4 v) {
    asm volatile("red.global.v4.f32.add [%0], {%1, %2, %3, %4};"
                 :: "l"(addr), "f"(v.x), "f"(v.y), "f"(v.z), "f"(v.w)
                 : "memory");
}

__device__ __forceinline__ float4 ldcs_f4(const float4* p) {
    float4 v;
    asm volatile("ld.global.cs.v4.f32 {%0, %1, %2, %3}, [%4];"
                 : "=f"(v.x), "=f"(v.y), "=f"(v.z), "=f"(v.w) : "l"(p));
    return v;
}

// 8 lanes per edge, 2 edges per thread (e, e+nh); only edges with
// dst in [lo,hi) are processed this pass.
__global__ void scatter_chunk_kernel(const float4* __restrict__ feat,
                                     const int* __restrict__ s_idx,
                                     const int* __restrict__ d_idx,
                                     float* __restrict__ out,
                                     int n_edges, int nh, int lo, int hi) {
    long long gid = blockIdx.x * (long long)blockDim.x + threadIdx.x;
    int pair = (int)(gid >> 3);
    if (pair >= nh) return;
    int sub = (int)(gid & 7);

    int e0 = pair;
    int e1 = pair + nh;
    bool has1 = (e1 < n_edges);

    int d0 = __ldcs(d_idx + e0);
    int d1 = has1 ? __ldcs(d_idx + e1) : -1;
    bool p0 = (d0 >= lo) & (d0 < hi);
    bool p1 = has1 & (d1 >= lo) & (d1 < hi);
    if (!(p0 | p1)) return;

    int s0 = p0 ? __ldcs(s_idx + e0) : 0;
    int s1 = p1 ? __ldcs(s_idx + e1) : 0;

    float4 v0, v1;
    if (p0) v0 = ldcs_f4(feat + (long long)s0 * 8 + sub);   // evict-first
    if (p1) v1 = ldcs_f4(feat + (long long)s1 * 8 + sub);

    if (p0) red_add_v4(out + (long long)d0 * FEAT_D + sub * 4, v0);
    if (p1) red_add_v4(out + (long long)d1 * FEAT_D + sub * 4, v1);
}

static inline void launch_block(const float* feat, const int* s, const int* d,
                                float* out_blk, int n_edges, int n_rows) {
    int nh = (n_edges + 1) / 2;
    long long threads = (long long)nh * 8;
    int sgrid = (int)((threads + 255) / 256);

    for (int lo = 0; lo < n_rows; lo += CHUNK_ROWS) {
        int hi = min(lo + CHUNK_ROWS, n_rows);
        long long n4 = (long long)(hi - lo) * 8;           // float4 in chunk
        zero_f4_kernel<<<(int)((n4 + 255) / 256), 256>>>(
            (float4*)(out_blk + (long long)lo * FEAT_D), n4);
        scatter_chunk_kernel<<<sgrid, 256>>>((const float4*)feat, s, d,
                                             out_blk, n_edges, nh, lo, hi);
    }
}

extern "C" void kernel_launch(void* const* d_in, const int* in_sizes, int n_in,
                              void* d_out, int out_size) {
    const float* u2 = (const float*)d_in[0];
    const float* u3 = (const float*)d_in[1];

    const int* s_b0a = (const int*)d_in[2];
    const int* d_b0a = (const int*)d_in[3];
    const int* s_b1a = (const int*)d_in[4];
    const int* d_b1a = (const int*)d_in[5];
    const int* s_b0t = (const int*)d_in[6];
    const int* d_b0t = (const int*)d_in[7];
    const int* s_b1t = (const int*)d_in[8];
    const int* d_b1t = (const int*)d_in[9];
    const int* s_b2t = (const int*)d_in[10];
    const int* d_b2t = (const int*)d_in[11];
    const int* s_a0t = (const int*)d_in[12];
    const int* d_a0t = (const int*)d_in[13];
    const int* s_a1t = (const int*)d_in[14];
    const int* d_a1t = (const int*)d_in[15];

    const int N3 = in_sizes[2];
    const int N4 = in_sizes[6];

    float* out = (float*)d_out;
    const long long blk3 = (long long)N3 * FEAT_D;
    const long long blk4 = (long long)N4 * FEAT_D;

    float* o = out;
    launch_block(u2, s_b0a, d_b0a, o, N3, N3); o += blk3;  // u_left
    launch_block(u2, s_b1a, d_b1a, o, N3, N3); o += blk3;  // u_right
    launch_block(u2, s_b0t, d_b0t, o, N4, N4); o += blk4;  // u_bond_left
    launch_block(u2, s_b1t, d_b1t, o, N4, N4); o += blk4;  // u_bond_center
    launch_block(u2, s_b2t, d_b2t, o, N4, N4); o += blk4;  // u_bond_right
    launch_block(u3, s_a0t, d_a0t, o, N4, N4); o += blk4;  // u_angle_left
    launch_block(u3, s_a1t, d_a1t, o, N4, N4);             // u_angle_right
}

// round 8
// speedup vs baseline: 1.0003x; 1.0003x over previous
#include <cuda_runtime.h>

// ---------------------------------------------------------------------------
// CarryII R7: R6 + dst-chunked zero/scatter to eliminate atomic RFO reads.
// Per relation: for each ~64MB chunk of output rows [lo,hi):
//   1) zero the chunk (dirty lines stay in 126MB L2),
//   2) scatter pass over ALL edges, predicated on dst in [lo,hi).
// REDs then hit L2-dirty lines -> no DRAM read-for-ownership; each output
// line does exactly one DRAM write (the eventual writeback).
// Gathers use __ldcs (evict-first) so feature lines don't evict the chunk.
// Extra cost: d_idx re-read once per chunk (~8MB << RFO saved).
// ---------------------------------------------------------------------------

static constexpr int FEAT_D = 32;
static constexpr int CHUNK_ROWS = 512 * 1024;   // 512k rows * 128B = 64 MB

__global__ void zero_f4_kernel(float4* __restrict__ out, long long n4) {
    long long i = blockIdx.x * (long long)blockDim.x + threadIdx.x;
    if (i < n4) out[i] = make_float4(0.f, 0.f, 0.f, 0.f);
}

__device__ __forceinline__ void red_add_v4(float* addr, float4 v) {
    asm volatile("red.global.v4.f32.add [%0], {%1, %2, %3, %4};"
                 :: "l"(addr), "f"(v.x), "f"(v.y), "f"(v.z), "f"(v.w)
                 : "memory");
}

__device__ __forceinline__ float4 ldcs_f4(const float4* p) {
    float4 v;
    asm volatile("ld.global.cs.v4.f32 {%0, %1, %2, %3}, [%4];"
                 : "=f"(v.x), "=f"(v.y), "=f"(v.z), "=f"(v.w) : "l"(p));
    return v;
}

// 8 lanes per edge, 2 edges per thread (e, e+nh); only edges with
// dst in [lo,hi) are processed this pass.
__global__ void scatter_chunk_kernel(const float4* __restrict__ feat,
                                     const int* __restrict__ s_idx,
                                     const int* __restrict__ d_idx,
                                     float* __restrict__ out,
                                     int n_edges, int nh, int lo, int hi) {
    long long gid = blockIdx.x * (long long)blockDim.x + threadIdx.x;
    int pair = (int)(gid >> 3);
    if (pair >= nh) return;
    int sub = (int)(gid & 7);

    int e0 = pair;
    int e1 = pair + nh;
    bool has1 = (e1 < n_edges);

    int d0 = __ldcs(d_idx + e0);
    int d1 = has1 ? __ldcs(d_idx + e1) : -1;
    bool p0 = (d0 >= lo) & (d0 < hi);
    bool p1 = has1 & (d1 >= lo) & (d1 < hi);
    if (!(p0 | p1)) return;

    int s0 = p0 ? __ldcs(s_idx + e0) : 0;
    int s1 = p1 ? __ldcs(s_idx + e1) : 0;

    float4 v0, v1;
    if (p0) v0 = ldcs_f4(feat + (long long)s0 * 8 + sub);   // evict-first
    if (p1) v1 = ldcs_f4(feat + (long long)s1 * 8 + sub);

    if (p0) red_add_v4(out + (long long)d0 * FEAT_D + sub * 4, v0);
    if (p1) red_add_v4(out + (long long)d1 * FEAT_D + sub * 4, v1);
}

static inline void launch_block(const float* feat, const int* s, const int* d,
                                float* out_blk, int n_edges, int n_rows) {
    int nh = (n_edges + 1) / 2;
    long long threads = (long long)nh * 8;
    int sgrid = (int)((threads + 255) / 256);

    for (int lo = 0; lo < n_rows; lo += CHUNK_ROWS) {
        int hi = min(lo + CHUNK_ROWS, n_rows);
        long long n4 = (long long)(hi - lo) * 8;           // float4 in chunk
        zero_f4_kernel<<<(int)((n4 + 255) / 256), 256>>>(
            (float4*)(out_blk + (long long)lo * FEAT_D), n4);
        scatter_chunk_kernel<<<sgrid, 256>>>((const float4*)feat, s, d,
                                             out_blk, n_edges, nh, lo, hi);
    }
}

extern "C" void kernel_launch(void* const* d_in, const int* in_sizes, int n_in,
                              void* d_out, int out_size) {
    const float* u2 = (const float*)d_in[0];
    const float* u3 = (const float*)d_in[1];

    const int* s_b0a = (const int*)d_in[2];
    const int* d_b0a = (const int*)d_in[3];
    const int* s_b1a = (const int*)d_in[4];
    const int* d_b1a = (const int*)d_in[5];
    const int* s_b0t = (const int*)d_in[6];
    const int* d_b0t = (const int*)d_in[7];
    const int* s_b1t = (const int*)d_in[8];
    const int* d_b1t = (const int*)d_in[9];
    const int* s_b2t = (const int*)d_in[10];
    const int* d_b2t = (const int*)d_in[11];
    const int* s_a0t = (const int*)d_in[12];
    const int* d_a0t = (const int*)d_in[13];
    const int* s_a1t = (const int*)d_in[14];
    const int* d_a1t = (const int*)d_in[15];

    const int N3 = in_sizes[2];
    const int N4 = in_sizes[6];

    float* out = (float*)d_out;
    const long long blk3 = (long long)N3 * FEAT_D;
    const long long blk4 = (long long)N4 * FEAT_D;

    float* o = out;
    launch_block(u2, s_b0a, d_b0a, o, N3, N3); o += blk3;  // u_left
    launch_block(u2, s_b1a, d_b1a, o, N3, N3); o += blk3;  // u_right
    launch_block(u2, s_b0t, d_b0t, o, N4, N4); o += blk4;  // u_bond_left
    launch_block(u2, s_b1t, d_b1t, o, N4, N4); o += blk4;  // u_bond_center
    launch_block(u2, s_b2t, d_b2t, o, N4, N4); o += blk4;  // u_bond_right
    launch_block(u3, s_a0t, d_a0t, o, N4, N4); o += blk4;  // u_angle_left
    launch_block(u3, s_a1t, d_a1t, o, N4, N4);             // u_angle_right
}

// round 10
// speedup vs baseline: 1.7122x; 1.7117x over previous
#include <cuda_runtime.h>
#include <cstdint>

// ---------------------------------------------------------------------------
// CarryII R10: R6 structure (per-relation zero-then-scatter, red.global.v4) +
//  1) 4 edges per thread (more MLP; issue was 16%, latency exposed)
//  2) feat gathers biased L2-resident via createpolicy evict_last +
//     ld.global.nc.L2::cache_hint (ptxas rejects bare evict_last on v4.f32)
// Index loads stay __ldcs (read-once streaming).
// ---------------------------------------------------------------------------

static constexpr int FEAT_D = 32;

__global__ void zero_f4_kernel(float4* __restrict__ out, long long n4) {
    long long i = blockIdx.x * (long long)blockDim.x + threadIdx.x;
    if (i < n4) out[i] = make_float4(0.f, 0.f, 0.f, 0.f);
}

__device__ __forceinline__ void red_add_v4(float* addr, float4 v) {
    asm volatile("red.global.v4.f32.add [%0], {%1, %2, %3, %4};"
                 :: "l"(addr), "f"(v.x), "f"(v.y), "f"(v.z), "f"(v.w)
                 : "memory");
}

__device__ __forceinline__ uint64_t evict_last_policy() {
    uint64_t policy;
    asm volatile("createpolicy.fractional.L2::evict_last.b64 %0, 1.0;"
                 : "=l"(policy));
    return policy;
}

__device__ __forceinline__ float4 ld_hint_f4(const float4* p, uint64_t policy) {
    float4 v;
    asm volatile("ld.global.nc.L2::cache_hint.v4.f32 {%0, %1, %2, %3}, [%4], %5;"
                 : "=f"(v.x), "=f"(v.y), "=f"(v.z), "=f"(v.w)
                 : "l"(p), "l"(policy));
    return v;
}

// 8 lanes per edge, 4 edges per thread (e, e+nq, e+2nq, e+3nq).
__global__ void scatter_add_v4x4_kernel(const float4* __restrict__ feat,
                                        const int* __restrict__ s_idx,
                                        const int* __restrict__ d_idx,
                                        float* __restrict__ out,
                                        int n_edges, int nq) {
    long long gid = blockIdx.x * (long long)blockDim.x + threadIdx.x;
    int q = (int)(gid >> 3);
    if (q >= nq) return;
    int sub = (int)(gid & 7);

    uint64_t pol = evict_last_policy();

    int e[4];
    bool p[4];
    #pragma unroll
    for (int k = 0; k < 4; k++) {
        e[k] = q + k * nq;
        p[k] = (e[k] < n_edges);
    }

    int s[4], d[4];
    #pragma unroll
    for (int k = 0; k < 4; k++) {
        s[k] = p[k] ? __ldcs(s_idx + e[k]) : 0;
        d[k] = p[k] ? __ldcs(d_idx + e[k]) : 0;
    }

    float4 v[4];
    #pragma unroll
    for (int k = 0; k < 4; k++)
        if (p[k]) v[k] = ld_hint_f4(feat + (long long)s[k] * 8 + sub, pol);

    #pragma unroll
    for (int k = 0; k < 4; k++)
        if (p[k]) red_add_v4(out + (long long)d[k] * FEAT_D + sub * 4, v[k]);
}

static inline void launch_block(const float* feat, const int* s, const int* d,
                                float* out_blk, int n_edges, int n_rows) {
    // zero this block right before scattering (dirty-in-L2 tail absorbs RFO)
    long long n4 = (long long)n_rows * 8;
    zero_f4_kernel<<<(int)((n4 + 255) / 256), 256>>>((float4*)out_blk, n4);

    int nq = (n_edges + 3) / 4;
    long long threads = (long long)nq * 8;
    int grid = (int)((threads + 255) / 256);
    scatter_add_v4x4_kernel<<<grid, 256>>>((const float4*)feat, s, d,
                                           out_blk, n_edges, nq);
}

extern "C" void kernel_launch(void* const* d_in, const int* in_sizes, int n_in,
                              void* d_out, int out_size) {
    const float* u2 = (const float*)d_in[0];
    const float* u3 = (const float*)d_in[1];

    const int* s_b0a = (const int*)d_in[2];
    const int* d_b0a = (const int*)d_in[3];
    const int* s_b1a = (const int*)d_in[4];
    const int* d_b1a = (const int*)d_in[5];
    const int* s_b0t = (const int*)d_in[6];
    const int* d_b0t = (const int*)d_in[7];
    const int* s_b1t = (const int*)d_in[8];
    const int* d_b1t = (const int*)d_in[9];
    const int* s_b2t = (const int*)d_in[10];
    const int* d_b2t = (const int*)d_in[11];
    const int* s_a0t = (const int*)d_in[12];
    const int* d_a0t = (const int*)d_in[13];
    const int* s_a1t = (const int*)d_in[14];
    const int* d_a1t = (const int*)d_in[15];

    const int N3 = in_sizes[2];
    const int N4 = in_sizes[6];

    float* out = (float*)d_out;
    const long long blk3 = (long long)N3 * FEAT_D;
    const long long blk4 = (long long)N4 * FEAT_D;

    float* o = out;
    launch_block(u2, s_b0a, d_b0a, o, N3, N3); o += blk3;  // u_left
    launch_block(u2, s_b1a, d_b1a, o, N3, N3); o += blk3;  // u_right
    launch_block(u2, s_b0t, d_b0t, o, N4, N4); o += blk4;  // u_bond_left
    launch_block(u2, s_b1t, d_b1t, o, N4, N4); o += blk4;  // u_bond_center
    launch_block(u2, s_b2t, d_b2t, o, N4, N4); o += blk4;  // u_bond_right
    launch_block(u3, s_a0t, d_a0t, o, N4, N4); o += blk4;  // u_angle_left
    launch_block(u3, s_a1t, d_a1t, o, N4, N4);             // u_angle_right
}